// round 6
// baseline (speedup 1.0000x reference)
#include <cuda_runtime.h>
#include <cuda_bf16.h>

#define NUM_SKILLS 300
#define EMB 256
#define CD 64
#define D3 21          // skill / attempt encoder width
#define DM 22          // mastery encoder width
#define BATCH 512
#define SEQ 200

// FROZEN (R4 design, re-audited R5): single fused kernel.
//   Phase A: load row (q,r) -> packed keys in smem; simultaneously collapse the
//            [EMB,64] projection to 4 per-e coefficients in smem:
//            traj[e] = q*A[e] + attempts*B[e] + mastery*C[e] + D[e]
//            (streamed accumulation, no Pr[] staging array -> no register spill)
//   Phase 1: running per-skill counts via O(t) broadcast-LDS scan
//   Phase 2: masked affine, coalesced float4 streaming stores (~105 MB, DRAM-bound)
__global__ __launch_bounds__(256, 4)   // occ 4 = single wave for 512 CTAs; <=64 regs
void traj_fused_kernel(const int* __restrict__ q, const int* __restrict__ r,
                       const float* __restrict__ skill_w, const float* __restrict__ skill_b,
                       const float* __restrict__ att_w,   const float* __restrict__ att_b,
                       const float* __restrict__ mast_w,  const float* __restrict__ mast_b,
                       const float* __restrict__ proj_w,  const float* __restrict__ proj_b,
                       float* __restrict__ out) {
    __shared__ int   pk[SEQ];        // (q<<1)|r if valid else -2
    __shared__ float att_s[SEQ];
    __shared__ float mast_s[SEQ];
    __shared__ float qf_s[SEQ];
    __shared__ float vf_s[SEQ];
    __shared__ __align__(16) float sA[EMB];
    __shared__ __align__(16) float sB[EMB];
    __shared__ __align__(16) float sC[EMB];
    __shared__ __align__(16) float sD[EMB];

    const int b = blockIdx.x;
    const int t = threadIdx.x;

    // ---- Phase A1: load row, pack key ----
    if (t < SEQ) {
        int qv = __ldg(q + b * SEQ + t);
        int rv = __ldg(r + b * SEQ + t);
        bool v = (qv >= 0) && (qv < NUM_SKILLS);
        pk[t]   = v ? ((qv << 1) | (rv & 1)) : -2;
        qf_s[t] = (float)qv;
        vf_s[t] = v ? 1.0f : 0.0f;
    }

    // ---- Phase A2: collapse projection for e = t (all 256 threads) ----
    // Fully unrolled: column index c is compile-time, so the A/B/C accumulator
    // choice and weight array selection are static. Each float4 of proj_w is
    // consumed immediately -> no 64-float staging array, no spills.
    {
        const float4* P4 = reinterpret_cast<const float4*>(proj_w + t * CD); // [EMB,64] row-major
        float A = 0.f, Bv = 0.f, Cv = 0.f, D = __ldg(proj_b + t);
        #pragma unroll
        for (int i = 0; i < CD / 4; ++i) {
            const float4 v4 = __ldg(P4 + i);
            const float pe[4] = {v4.x, v4.y, v4.z, v4.w};
            #pragma unroll
            for (int j = 0; j < 4; ++j) {
                const int c = 4 * i + j;            // compile-time constant
                if (c < D3) {
                    A = fmaf(__ldg(skill_w + c),          pe[j], A);
                    D = fmaf(__ldg(skill_b + c),          pe[j], D);
                } else if (c < 2 * D3) {
                    Bv = fmaf(__ldg(att_w + (c - D3)),    pe[j], Bv);
                    D  = fmaf(__ldg(att_b + (c - D3)),    pe[j], D);
                } else {
                    Cv = fmaf(__ldg(mast_w + (c - 2*D3)), pe[j], Cv);
                    D  = fmaf(__ldg(mast_b + (c - 2*D3)), pe[j], D);
                }
            }
        }
        sA[t] = A; sB[t] = Bv; sC[t] = Cv; sD[t] = D;
    }
    __syncthreads();

    // ---- Phase 1: running counts, O(t) per thread, broadcast LDS ----
    if (t < SEQ) {
        const int my = pk[t] & ~1;
        int a = 0, c = 0;
        for (int tp = 0; tp <= t; ++tp) {
            int p = pk[tp];
            bool hit = ((p & ~1) == my);
            a += hit;
            c += hit ? (p & 1) : 0;
        }
        att_s[t]  = (float)a;
        mast_s[t] = (float)c / fmaxf((float)a, 1.0f);
    }
    __syncthreads();

    // ---- Phase 2: masked affine, coalesced float4 streaming stores ----
    // e4 = t & 63 -> 64 consecutive float4 lanes (two warps cover a full 1KB row
    // segment); ssub = t >> 6 strides the sequence dimension by 4.
    const int e4   = t & 63;
    const int ssub = t >> 6;
    const float4 cA = reinterpret_cast<const float4*>(sA)[e4];
    const float4 cB = reinterpret_cast<const float4*>(sB)[e4];
    const float4 cC = reinterpret_cast<const float4*>(sC)[e4];
    const float4 cD = reinterpret_cast<const float4*>(sD)[e4];

    float4* __restrict__ o = reinterpret_cast<float4*>(out) + (size_t)b * SEQ * (EMB / 4);

    #pragma unroll 2
    for (int s = ssub; s < SEQ; s += 4) {
        const float a  = att_s[s];
        const float m  = mast_s[s];
        const float qf = qf_s[s];
        const float v  = vf_s[s];
        float4 res;
        res.x = fmaf(qf, cA.x, fmaf(a, cB.x, fmaf(m, cC.x, cD.x)));
        res.y = fmaf(qf, cA.y, fmaf(a, cB.y, fmaf(m, cC.y, cD.y)));
        res.z = fmaf(qf, cA.z, fmaf(a, cB.z, fmaf(m, cC.z, cD.z)));
        res.w = fmaf(qf, cA.w, fmaf(a, cB.w, fmaf(m, cC.w, cD.w)));
        if (v == 0.0f) { res.x = 0.f; res.y = 0.f; res.z = 0.f; res.w = 0.f; }
        __stcs(o + s * (EMB / 4) + e4, res);   // streaming: write-once, bypass L2 retention
    }
}

extern "C" void kernel_launch(void* const* d_in, const int* in_sizes, int n_in,
                              void* d_out, int out_size) {
    const int*   q       = (const int*)d_in[0];
    const int*   r       = (const int*)d_in[1];
    /* d_in[2] = qry — unused by the reference computation */
    const float* skill_w = (const float*)d_in[3];
    const float* skill_b = (const float*)d_in[4];
    const float* att_w   = (const float*)d_in[5];
    const float* att_b   = (const float*)d_in[6];
    const float* mast_w  = (const float*)d_in[7];
    const float* mast_b  = (const float*)d_in[8];
    const float* proj_w  = (const float*)d_in[9];
    const float* proj_b  = (const float*)d_in[10];

    traj_fused_kernel<<<BATCH, 256>>>(q, r, skill_w, skill_b, att_w, att_b,
                                      mast_w, mast_b, proj_w, proj_b, (float*)d_out);
}

// round 12
// speedup vs baseline: 1.1317x; 1.1317x over previous
#include <cuda_runtime.h>
#include <cuda_bf16.h>

#define NUM_SKILLS 300
#define EMB 256
#define CD 64
#define D3 21          // skill / attempt encoder width
#define DM 22          // mastery encoder width
#define BATCH 512
#define SEQ 200
#define ROWS (BATCH * SEQ)        // 102400 (b,s) positions
#define E4 (EMB / 4)              // 64 float4 lanes per position

// Scratch (device globals — no allocs allowed in kernel_launch)
__device__ __align__(16) float4 g_row[ROWS];   // (qf, attempts, mastery, valid)  1.6 MB, L2-resident
__device__ __align__(16) float4 g_cA4[E4];     // collapsed projection coefficients
__device__ __align__(16) float4 g_cB4[E4];
__device__ __align__(16) float4 g_cC4[E4];
__device__ __align__(16) float4 g_cD4[E4];

// ---------------------------------------------------------------------------
// Kernel A: per-row running counts (blocks 0..BATCH-1) + coef collapse (block BATCH)
// ---------------------------------------------------------------------------
__global__ __launch_bounds__(256)
void prep_kernel(const int* __restrict__ q, const int* __restrict__ r,
                 const float* __restrict__ skill_w, const float* __restrict__ skill_b,
                 const float* __restrict__ att_w,   const float* __restrict__ att_b,
                 const float* __restrict__ mast_w,  const float* __restrict__ mast_b,
                 const float* __restrict__ proj_w,  const float* __restrict__ proj_b) {
    const int t = threadIdx.x;

    if (blockIdx.x == BATCH) {
        // ---- coef collapse: traj[e] = qf*A[e] + att*B[e] + mast*C[e] + D[e] ----
        // Fully unrolled; column index compile-time -> static accumulator dispatch, no spills.
        const float4* P4 = reinterpret_cast<const float4*>(proj_w + t * CD); // [EMB,64] row-major
        float A = 0.f, Bv = 0.f, Cv = 0.f, D = __ldg(proj_b + t);
        #pragma unroll
        for (int i = 0; i < CD / 4; ++i) {
            const float4 v4 = __ldg(P4 + i);
            const float pe[4] = {v4.x, v4.y, v4.z, v4.w};
            #pragma unroll
            for (int j = 0; j < 4; ++j) {
                const int c = 4 * i + j;
                if (c < D3) {
                    A = fmaf(__ldg(skill_w + c),          pe[j], A);
                    D = fmaf(__ldg(skill_b + c),          pe[j], D);
                } else if (c < 2 * D3) {
                    Bv = fmaf(__ldg(att_w + (c - D3)),    pe[j], Bv);
                    D  = fmaf(__ldg(att_b + (c - D3)),    pe[j], D);
                } else {
                    Cv = fmaf(__ldg(mast_w + (c - 2*D3)), pe[j], Cv);
                    D  = fmaf(__ldg(mast_b + (c - 2*D3)), pe[j], D);
                }
            }
        }
        reinterpret_cast<float*>(g_cA4)[t] = A;
        reinterpret_cast<float*>(g_cB4)[t] = Bv;
        reinterpret_cast<float*>(g_cC4)[t] = Cv;
        reinterpret_cast<float*>(g_cD4)[t] = D;
        return;
    }

    // ---- running per-skill counts for row b ----
    __shared__ int pk[SEQ];   // (q<<1)|r if valid else -2
    const int b = blockIdx.x;

    int qv = 0, rv = 0;
    if (t < SEQ) {
        qv = __ldg(q + b * SEQ + t);
        rv = __ldg(r + b * SEQ + t);
        bool v = (qv >= 0) && (qv < NUM_SKILLS);
        pk[t] = v ? ((qv << 1) | (rv & 1)) : -2;
    }
    __syncthreads();

    if (t < SEQ) {
        const int my = pk[t] & ~1;
        const bool valid = my >= 0;
        int a = 0, c = 0;
        for (int tp = 0; tp <= t; ++tp) {
            int p = pk[tp];
            bool hit = ((p & ~1) == my);
            a += hit;
            c += hit ? (p & 1) : 0;
        }
        float af = (float)a;
        g_row[b * SEQ + t] = make_float4((float)qv, af,
                                         (float)c / fmaxf(af, 1.0f),
                                         valid ? 1.0f : 0.0f);
    }
}

// ---------------------------------------------------------------------------
// Kernel B: pure streaming store. thread -> (e4 = idx&63), 4 sequence positions.
// Warp: lanes span 32 consecutive e4 at a warp-uniform sidx -> 512B coalesced STG.128.
// Coefs live in registers across all 4 iterations; row scratch is a broadcast LDG.
// ---------------------------------------------------------------------------
#define SPT 4   // sequence positions per thread
__global__ __launch_bounds__(256, 6)
void store_kernel(float* __restrict__ out) {
    const int idx = blockIdx.x * 256 + threadIdx.x;
    const int e4  = idx & (E4 - 1);
    const int s0  = (idx >> 6) * SPT;          // first sidx this thread covers

    const float4 cA = g_cA4[e4];
    const float4 cB = g_cB4[e4];
    const float4 cC = g_cC4[e4];
    const float4 cD = g_cD4[e4];

    float4* __restrict__ o = reinterpret_cast<float4*>(out);

    #pragma unroll
    for (int k = 0; k < SPT; ++k) {
        const int sidx = s0 + k;               // 0..ROWS-1 (grid sized exactly)
        const float4 row = g_row[sidx];        // (qf, att, mast, vf) — warp-broadcast
        float4 res;
        res.x = row.w * fmaf(row.x, cA.x, fmaf(row.y, cB.x, fmaf(row.z, cC.x, cD.x)));
        res.y = row.w * fmaf(row.x, cA.y, fmaf(row.y, cB.y, fmaf(row.z, cC.y, cD.y)));
        res.z = row.w * fmaf(row.x, cA.z, fmaf(row.y, cB.z, fmaf(row.z, cC.z, cD.z)));
        res.w = row.w * fmaf(row.x, cA.w, fmaf(row.y, cB.w, fmaf(row.z, cC.w, cD.w)));
        o[(size_t)sidx * E4 + e4] = res;
    }
}

extern "C" void kernel_launch(void* const* d_in, const int* in_sizes, int n_in,
                              void* d_out, int out_size) {
    const int*   q       = (const int*)d_in[0];
    const int*   r       = (const int*)d_in[1];
    /* d_in[2] = qry — unused by the reference computation */
    const float* skill_w = (const float*)d_in[3];
    const float* skill_b = (const float*)d_in[4];
    const float* att_w   = (const float*)d_in[5];
    const float* att_b   = (const float*)d_in[6];
    const float* mast_w  = (const float*)d_in[7];
    const float* mast_b  = (const float*)d_in[8];
    const float* proj_w  = (const float*)d_in[9];
    const float* proj_b  = (const float*)d_in[10];

    prep_kernel<<<BATCH + 1, 256>>>(q, r, skill_w, skill_b, att_w, att_b,
                                    mast_w, mast_b, proj_w, proj_b);

    // ROWS * E4 float4 outputs; each thread writes SPT (along s), 256 thr/block
    const int blocksB = (ROWS / SPT) * E4 / 256;   // 102400/4*64/256 = 6400
    store_kernel<<<blocksB, 256>>>((float*)d_out);
}

// round 15
// speedup vs baseline: 1.1416x; 1.0088x over previous
#include <cuda_runtime.h>
#include <cuda_bf16.h>
#include <cstdint>

#define NUM_SKILLS 300
#define EMB 256
#define CD 64
#define D3 21          // skill / attempt encoder width
#define DM 22          // mastery encoder width
#define BATCH 512
#define SEQ 200
#define ROWS (BATCH * SEQ)        // 102400 (b,s) positions
#define E4 (EMB / 4)              // 64 float4 lanes per position
#define SPT 4                     // sequence positions per thread
#define TILE_S 16                 // sidx per block (4 sgroups * SPT)
#define TILE_BYTES (TILE_S * EMB * 4)   // 16384

// Scratch (device globals — no allocs allowed in kernel_launch)
__device__ __align__(16) float4 g_row[ROWS];   // (qf, attempts, mastery, valid)  1.6 MB, L2-resident
__device__ __align__(16) float4 g_cA4[E4];     // collapsed projection coefficients
__device__ __align__(16) float4 g_cB4[E4];
__device__ __align__(16) float4 g_cC4[E4];
__device__ __align__(16) float4 g_cD4[E4];

__device__ __forceinline__ uint32_t smem_u32(const void* p) {
    uint32_t a;
    asm("{ .reg .u64 tmp; cvta.to.shared.u64 tmp, %1; cvt.u32.u64 %0, tmp; }"
        : "=r"(a) : "l"(p));
    return a;
}

// ---------------------------------------------------------------------------
// Kernel A: per-row running counts (blocks 0..BATCH-1) + coef collapse (block BATCH)
// ---------------------------------------------------------------------------
__global__ __launch_bounds__(256)
void prep_kernel(const int* __restrict__ q, const int* __restrict__ r,
                 const float* __restrict__ skill_w, const float* __restrict__ skill_b,
                 const float* __restrict__ att_w,   const float* __restrict__ att_b,
                 const float* __restrict__ mast_w,  const float* __restrict__ mast_b,
                 const float* __restrict__ proj_w,  const float* __restrict__ proj_b) {
    const int t = threadIdx.x;

    if (blockIdx.x == BATCH) {
        // ---- coef collapse: traj[e] = qf*A[e] + att*B[e] + mast*C[e] + D[e] ----
        const float4* P4 = reinterpret_cast<const float4*>(proj_w + t * CD); // [EMB,64] row-major
        float A = 0.f, Bv = 0.f, Cv = 0.f, D = __ldg(proj_b + t);
        #pragma unroll
        for (int i = 0; i < CD / 4; ++i) {
            const float4 v4 = __ldg(P4 + i);
            const float pe[4] = {v4.x, v4.y, v4.z, v4.w};
            #pragma unroll
            for (int j = 0; j < 4; ++j) {
                const int c = 4 * i + j;            // compile-time constant
                if (c < D3) {
                    A = fmaf(__ldg(skill_w + c),          pe[j], A);
                    D = fmaf(__ldg(skill_b + c),          pe[j], D);
                } else if (c < 2 * D3) {
                    Bv = fmaf(__ldg(att_w + (c - D3)),    pe[j], Bv);
                    D  = fmaf(__ldg(att_b + (c - D3)),    pe[j], D);
                } else {
                    Cv = fmaf(__ldg(mast_w + (c - 2*D3)), pe[j], Cv);
                    D  = fmaf(__ldg(mast_b + (c - 2*D3)), pe[j], D);
                }
            }
        }
        reinterpret_cast<float*>(g_cA4)[t] = A;
        reinterpret_cast<float*>(g_cB4)[t] = Bv;
        reinterpret_cast<float*>(g_cC4)[t] = Cv;
        reinterpret_cast<float*>(g_cD4)[t] = D;
        return;
    }

    // ---- running per-skill counts for row b ----
    __shared__ int pk[SEQ];   // (q<<1)|r if valid else -2
    const int b = blockIdx.x;

    int qv = 0, rv = 0;
    if (t < SEQ) {
        qv = __ldg(q + b * SEQ + t);
        rv = __ldg(r + b * SEQ + t);
        bool v = (qv >= 0) && (qv < NUM_SKILLS);
        pk[t] = v ? ((qv << 1) | (rv & 1)) : -2;
    }
    __syncthreads();

    if (t < SEQ) {
        const int my = pk[t] & ~1;
        const bool valid = my >= 0;
        int a = 0, c = 0;
        for (int tp = 0; tp <= t; ++tp) {
            int p = pk[tp];
            bool hit = ((p & ~1) == my);
            a += hit;
            c += hit ? (p & 1) : 0;
        }
        float af = (float)a;
        g_row[b * SEQ + t] = make_float4((float)qv, af,
                                         (float)c / fmaxf(af, 1.0f),
                                         valid ? 1.0f : 0.0f);
    }
}

// ---------------------------------------------------------------------------
// Kernel B: compute tile in SMEM (cheap STS.128, 4 cyc/warp-op), then ship the
// whole 16KB tile with ONE cp.async.bulk (1D TMA store) — stores leave the LSU.
// Block b covers sidx [16b, 16b+16) x full EMB -> 16KB contiguous in gmem.
// ---------------------------------------------------------------------------
__global__ __launch_bounds__(256, 6)
void store_kernel(float* __restrict__ out) {
    __shared__ __align__(128) float4 tile[TILE_S * E4];   // 16 KB

    const int t  = threadIdx.x;
    const int e4 = t & (E4 - 1);
    const int tg = t >> 6;                    // 0..3 (sgroup within block)
    const int sbase = blockIdx.x * TILE_S;    // first sidx of this block

    const float4 cA = g_cA4[e4];
    const float4 cB = g_cB4[e4];
    const float4 cC = g_cC4[e4];
    const float4 cD = g_cD4[e4];

    // Prefetch all SPT row vectors first: MLP=4 before any dependent math.
    float4 row[SPT];
    #pragma unroll
    for (int k = 0; k < SPT; ++k)
        row[k] = g_row[sbase + tg * SPT + k];   // warp-broadcast LDG

    #pragma unroll
    for (int k = 0; k < SPT; ++k) {
        const float4 rw = row[k];
        float4 res;
        res.x = rw.w * fmaf(rw.x, cA.x, fmaf(rw.y, cB.x, fmaf(rw.z, cC.x, cD.x)));
        res.y = rw.w * fmaf(rw.x, cA.y, fmaf(rw.y, cB.y, fmaf(rw.z, cC.y, cD.y)));
        res.z = rw.w * fmaf(rw.x, cA.z, fmaf(rw.y, cB.z, fmaf(rw.z, cC.z, cD.z)));
        res.w = rw.w * fmaf(rw.x, cA.w, fmaf(rw.y, cB.w, fmaf(rw.z, cC.w, cD.w)));
        tile[(tg * SPT + k) * E4 + e4] = res;   // STS.128, conflict-free (lanes -> consecutive banks)
    }
    __syncthreads();

    if (t == 0) {
        asm volatile("fence.proxy.async.shared::cta;" ::: "memory");
        const uint32_t saddr = smem_u32(tile);
        float* gdst = out + (size_t)sbase * EMB;
        asm volatile(
            "cp.async.bulk.global.shared::cta.bulk_group [%0], [%1], %2;"
            :: "l"(gdst), "r"(saddr), "r"((uint32_t)TILE_BYTES) : "memory");
        asm volatile("cp.async.bulk.commit_group;" ::: "memory");
        asm volatile("cp.async.bulk.wait_group 0;" ::: "memory");
    }
}

extern "C" void kernel_launch(void* const* d_in, const int* in_sizes, int n_in,
                              void* d_out, int out_size) {
    const int*   q       = (const int*)d_in[0];
    const int*   r       = (const int*)d_in[1];
    /* d_in[2] = qry — unused by the reference computation */
    const float* skill_w = (const float*)d_in[3];
    const float* skill_b = (const float*)d_in[4];
    const float* att_w   = (const float*)d_in[5];
    const float* att_b   = (const float*)d_in[6];
    const float* mast_w  = (const float*)d_in[7];
    const float* mast_b  = (const float*)d_in[8];
    const float* proj_w  = (const float*)d_in[9];
    const float* proj_b  = (const float*)d_in[10];

    prep_kernel<<<BATCH + 1, 256>>>(q, r, skill_w, skill_b, att_w, att_b,
                                    mast_w, mast_b, proj_w, proj_b);

    store_kernel<<<ROWS / TILE_S, 256>>>((float*)d_out);   // 6400 blocks
}